// round 15
// baseline (speedup 1.0000x reference)
#include <cuda_runtime.h>
#include <math.h>

// SequenceSummary: B=16, S=2048, D=1024, H=16, hd=64, P=8, cls=1, recent=64, L=73
constexpr int Bn = 16;
constexpr int Sn = 2048;
constexpr int Dn = 1024;
constexpr int Hn = 16;
constexpr int HDn = 64;
constexpr int Pn = 8;
constexpr int Rn = 64;
constexpr int Ln = 73;          // 1 + 8 + 64
constexpr int Cn = 128;         // H * P
constexpr float LNEPS = 1e-5f;
constexpr int MPAD = 1280;      // summary rows padded up
constexpr int KSPLIT = 8;       // split-K factor for pooled GEMM
constexpr int PSPLIT = 2;       // split-K factor for pooling (attn@hidden)

// packed fp32 pair FMA: acc += a * b (elementwise on 2 packed floats)
__device__ __forceinline__ void fma_f32x2(unsigned long long& acc,
                                          unsigned long long a,
                                          unsigned long long b) {
#if !defined(__CUDA_ARCH__) || (__CUDA_ARCH__ >= 1000)
    asm("fma.rn.f32x2 %0, %1, %2, %0;" : "+l"(acc) : "l"(a), "l"(b));
#else
    unsigned int al, ah, bl, bh, cl, ch;
    asm("mov.b64 {%0, %1}, %2;" : "=r"(al), "=r"(ah) : "l"(a));
    asm("mov.b64 {%0, %1}, %2;" : "=r"(bl), "=r"(bh) : "l"(b));
    asm("mov.b64 {%0, %1}, %2;" : "=r"(cl), "=r"(ch) : "l"(acc));
    float x = fmaf(__uint_as_float(al), __uint_as_float(bl), __uint_as_float(cl));
    float y = fmaf(__uint_as_float(ah), __uint_as_float(bh), __uint_as_float(ch));
    asm("mov.b64 %0, {%1, %2};" : "=l"(acc)
        : "r"(__float_as_uint(x)), "r"(__float_as_uint(y)));
#endif
}

__device__ __forceinline__ void unpack2(unsigned long long v, float& lo, float& hi) {
    unsigned int l, h;
    asm("mov.b64 {%0, %1}, %2;" : "=r"(l), "=r"(h) : "l"(v));
    lo = __uint_as_float(l); hi = __uint_as_float(h);
}

// block-wide sum over 256 threads (all threads must participate)
__device__ __forceinline__ float blk_sum(float v, float* red, int tid) {
    red[tid] = v; __syncthreads();
    for (int o = 128; o > 0; o >>= 1) { if (tid < o) red[tid] += red[tid + o]; __syncthreads(); }
    float r = red[0]; __syncthreads();
    return r;
}

// ---------------- scratch (static __device__ arrays; no allocation) ----------------
__device__ float g_q[Pn * Dn];
__device__ float g_qtilT[Dn * Cn];      // [d][c], c = h*8+p, pre-scaled by 1/sqrt(hd)
__device__ float g_scores[Cn * Bn * Sn];   // transposed: [c][b*S+s]
__device__ float g_attn[Bn * Cn * Sn];     // [b][c][s]
__device__ float g_ph[PSPLIT * Bn * Cn * Dn]; // pooling split-K partials
__device__ float g_ctx[Bn * Pn * Dn];
__device__ float g_part[KSPLIT * Cn * Dn]; // split-K partials for pooled proj
__device__ float g_WtO[Dn * Dn];           // out_w^T as [o][j]
__device__ float g_WtVG[Dn * 2 * Dn];      // [d][0:1024]=WtV*g, [d][1024:2048]=WtG*g
__device__ float g_biasVG[2 * Dn];
__device__ float g_xhat[MPAD * Dn];
__device__ float g_vg[MPAD * 2 * Dn];      // fused val|gate pre-activation
__device__ float g_maskf[Bn * Ln];
__device__ int   g_len[Bn];

// ---------------- utility kernels ----------------
__global__ void k_zero(float* p, int n) {
    for (int i = blockIdx.x * blockDim.x + threadIdx.x; i < n; i += gridDim.x * blockDim.x)
        p[i] = 0.f;
}

// Detect valid_mask dtype (bool/int32/float32) from byte patterns inside the
// minimum-size region (first 32KB), then count per-row lengths (mask is prefix form).
__global__ void k_lengths(const unsigned char* __restrict__ mask) {
    __shared__ int s_flags[2];
    int tid = threadIdx.x;
    if (tid < 2) s_flags[tid] = 0;
    __syncthreads();
    const unsigned int* w = (const unsigned int*)mask;
    int isF = 0, isB = 0;
    for (int i = tid; i < (Bn * Sn) / 4; i += 256) {
        unsigned int v = w[i];
        if (v == 0x3F800000u) isF = 1;
        else if (v != 0u && v != 1u) isB = 1;
    }
    if (isF) atomicOr(&s_flags[0], 1);
    if (isB) atomicOr(&s_flags[1], 1);
    __syncthreads();
    int kind = s_flags[0] ? 2 : (s_flags[1] ? 0 : 1);  // 0=bool 1=int32 2=float32
    int row = tid / 16, lane = tid & 15;
    int cnt = 0;
    if (kind == 0) {
        const unsigned char* r = mask + row * Sn;
        for (int s = lane; s < Sn; s += 16) cnt += (r[s] != 0);
    } else {
        const unsigned int* r = w + row * Sn;
        for (int s = lane; s < Sn; s += 16) cnt += (r[s] != 0);
    }
    for (int off = 8; off > 0; off >>= 1) cnt += __shfl_down_sync(0xffffffffu, cnt, off, 16);
    if (lane == 0) g_len[row] = cnt;
}

// q = queries @ Wq^T + bq  -> g_q [P][D]  (float4 dot: lane reads 16B, 512B/warp/iter)
__global__ void k_qproj(const float* __restrict__ q, const float* __restrict__ W,
                        const float* __restrict__ bq) {
    int warp = threadIdx.x >> 5, lane = threadIdx.x & 31;
    int out = blockIdx.x * 8 + warp;
    int p = out >> 10, i = out & 1023;
    const float4* q4 = (const float4*)(q + p * Dn);
    const float4* w4 = (const float4*)(W + (long)i * Dn);
    float acc = 0.f;
#pragma unroll
    for (int d4 = lane; d4 < Dn / 4; d4 += 32) {
        float4 a = q4[d4];
        float4 b = w4[d4];
        acc += a.x * b.x + a.y * b.y + a.z * b.z + a.w * b.w;
    }
    for (int off = 16; off > 0; off >>= 1) acc += __shfl_down_sync(0xffffffffu, acc, off);
    if (lane == 0) g_q[out] = acc + bq[i];
}

// qtilT[d..d+3][c] = (1/8) * sum_j qh[p,h,j] * Wk[h*64+j][d..d+3]  (float4 over d)
// NOTE: the k-projection bias bk would add a per-c constant to every score row;
// softmax is shift-invariant so it is dropped exactly.
__global__ void k_qtil(const float* __restrict__ Wk) {
    int tid = threadIdx.x;         // 256 threads, each owns 4 consecutive d
    int c = blockIdx.x;            // 128 channels
    int p = c & 7, h = c >> 3;
    int d = tid * 4;
    float4 acc = make_float4(0.f, 0.f, 0.f, 0.f);
#pragma unroll 8
    for (int j = 0; j < HDn; j++) {
        float qv = g_q[p * Dn + h * HDn + j];
        float4 wv = *(const float4*)(Wk + (long)(h * HDn + j) * Dn + d);
        acc.x += qv * wv.x; acc.y += qv * wv.y;
        acc.z += qv * wv.z; acc.w += qv * wv.w;
    }
    g_qtilT[(long)(d + 0) * Cn + c] = acc.x * 0.125f;
    g_qtilT[(long)(d + 1) * Cn + c] = acc.y * 0.125f;
    g_qtilT[(long)(d + 2) * Cn + c] = acc.z * 0.125f;
    g_qtilT[(long)(d + 3) * Cn + c] = acc.w * 0.125f;
}

// merged transpose+scale: z=0 WtV*lnvg -> WtVG[:,0:1024]; z=1 WtG*lngg -> WtVG[:,1024:2048];
// z=2 out_w -> WtO
__global__ void k_transpose3(const float* __restrict__ Wv, const float* __restrict__ lnvg,
                             const float* __restrict__ Wg, const float* __restrict__ lngg,
                             const float* __restrict__ outw,
                             float* __restrict__ dWtVG, float* __restrict__ dWtO) {
    __shared__ float t[32][33];
    int z = blockIdx.z;
    const float* src = (z == 0) ? Wv : (z == 1) ? Wg : outw;
    const float* scale = (z == 0) ? lnvg : (z == 1) ? lngg : nullptr;
    float* dst = (z == 2) ? dWtO : dWtVG;
    int ldd = (z == 2) ? Dn : 2 * Dn;
    int coloff = (z == 1) ? Dn : 0;
    int bx = blockIdx.x * 32, by = blockIdx.y * 32;
    int txd = threadIdx.x, tyd = threadIdx.y;
    for (int i = 0; i < 32; i += 8)
        t[tyd + i][txd] = src[(long)(by + tyd + i) * Dn + bx + txd];
    __syncthreads();
    for (int i = 0; i < 32; i += 8) {
        int drow = bx + tyd + i;
        float sc = scale ? scale[drow] : 1.f;
        dst[(long)drow * ldd + coloff + by + txd] = t[txd][tyd + i] * sc;
    }
}

// merged bias fold: oo in [0,2048): first half -> biasVG[o] from Wv/lnvb/bv,
// second -> biasVG[Dn+o] from Wg/lngb/bg
__global__ void k_bias2(float* __restrict__ out,
                        const float* __restrict__ Wv, const float* __restrict__ lnvb,
                        const float* __restrict__ bv,
                        const float* __restrict__ Wg, const float* __restrict__ lngb,
                        const float* __restrict__ bg) {
    int oo = blockIdx.x, tid = threadIdx.x;
    int o = oo & (Dn - 1);
    const float* W = (oo < Dn) ? Wv : Wg;
    const float* lnb = (oo < Dn) ? lnvb : lngb;
    const float* bb = (oo < Dn) ? bv : bg;
    __shared__ float red[256];
    float acc = 0.f;
    for (int d = tid; d < Dn; d += 256) acc += W[(long)o * Dn + d] * lnb[d];
    float r = blk_sum(acc, red, tid);
    if (tid == 0) out[oo] = r + bb[o];
}

// ---------------- generic tiled SGEMM: C = A@B (+bias) ----------------
// BM x 128 tiles, BK=16, 256 threads, MI x 8 microtile, double-buffered smem,
// packed f32x2 FMA. EPI: 0 = plain (float4 stores), 3 = transposed store C[n][m]
// via smem staging (EPI=3 requires BM=128, N=128, M % 128 == 0).
// blockIdx.z decomposes as z1 = z/zdiv (stride sA/sB/sC), z2 = z%zdiv (stride s*2).
template <int EPI, int BM>
__global__ void __launch_bounds__(256)
k_gemm(const float* __restrict__ A, const float* __restrict__ Bm, float* __restrict__ C,
       int M, int N, int K, int lda, int ldb, int ldc, int zdiv,
       long sA, long sA2, long sB, long sB2, long sC, long sC2,
       const float* __restrict__ bias) {
    constexpr int MI = BM / 16;   // 8 for BM=128, 4 for BM=64
    int z1 = blockIdx.z / zdiv, z2 = blockIdx.z - z1 * zdiv;
    A += z1 * sA + z2 * sA2; Bm += z1 * sB + z2 * sB2; C += z1 * sC + z2 * sC2;
    int m0 = blockIdx.y * BM, n0 = blockIdx.x * 128;
    __shared__ float As[2][16][BM];
    __shared__ float Bs[2][16][128];
    int tid = threadIdx.x;
    int tx = tid & 15, ty = tid >> 4;

    int arow0 = tid >> 2, akc0 = (tid & 3) * 4;
    int arow1 = arow0 + 64;
    int bkr0 = tid >> 5, bnc0 = (tid & 31) * 4;
    int bkr1 = bkr0 + 8;

    unsigned long long acc2[MI][4];
#pragma unroll
    for (int i = 0; i < MI; i++)
#pragma unroll
        for (int j = 0; j < 4; j++) acc2[i][j] = 0ull;

    // prologue
    float4 pa0 = make_float4(0.f, 0.f, 0.f, 0.f), pa1 = pa0;
    if (m0 + arow0 < M) pa0 = *(const float4*)(A + (long)(m0 + arow0) * lda + akc0);
    if constexpr (BM == 128)
        if (m0 + arow1 < M) pa1 = *(const float4*)(A + (long)(m0 + arow1) * lda + akc0);
    float4 pb0 = *(const float4*)(Bm + (long)bkr0 * ldb + n0 + bnc0);
    float4 pb1 = *(const float4*)(Bm + (long)bkr1 * ldb + n0 + bnc0);
    As[0][akc0 + 0][arow0] = pa0.x; As[0][akc0 + 1][arow0] = pa0.y;
    As[0][akc0 + 2][arow0] = pa0.z; As[0][akc0 + 3][arow0] = pa0.w;
    if constexpr (BM == 128) {
        As[0][akc0 + 0][arow1] = pa1.x; As[0][akc0 + 1][arow1] = pa1.y;
        As[0][akc0 + 2][arow1] = pa1.z; As[0][akc0 + 3][arow1] = pa1.w;
    }
    *(float4*)(&Bs[0][bkr0][bnc0]) = pb0;
    *(float4*)(&Bs[0][bkr1][bnc0]) = pb1;
    __syncthreads();

    int cur = 0;
    for (int k0 = 0; k0 < K; k0 += 16) {
        bool more = (k0 + 16) < K;
        if (more) {
            int kn = k0 + 16;
            pa0 = make_float4(0.f, 0.f, 0.f, 0.f); pa1 = pa0;
            if (m0 + arow0 < M) pa0 = *(const float4*)(A + (long)(m0 + arow0) * lda + kn + akc0);
            if constexpr (BM == 128)
                if (m0 + arow1 < M) pa1 = *(const float4*)(A + (long)(m0 + arow1) * lda + kn + akc0);
            pb0 = *(const float4*)(Bm + (long)(kn + bkr0) * ldb + n0 + bnc0);
            pb1 = *(const float4*)(Bm + (long)(kn + bkr1) * ldb + n0 + bnc0);
        }
#pragma unroll
        for (int kk = 0; kk < 16; kk++) {
            float a[MI];
            *(float4*)&a[0] = *(const float4*)(&As[cur][kk][ty * 4]);
            if constexpr (BM == 128)
                *(float4*)&a[4] = *(const float4*)(&As[cur][kk][ty * 4 + 64]);
            unsigned long long ad[MI];
#pragma unroll
            for (int i = 0; i < MI; i++) {
                unsigned int ai = __float_as_uint(a[i]);
                asm("mov.b64 %0, {%1, %1};" : "=l"(ad[i]) : "r"(ai));
            }
            unsigned long long b2[4];
            b2[0] = *(const unsigned long long*)(&Bs[cur][kk][tx * 4]);
            b2[1] = *(const unsigned long long*)(&Bs[cur][kk][tx * 4 + 2]);
            b2[2] = *(const unsigned long long*)(&Bs[cur][kk][tx * 4 + 64]);
            b2[3] = *(const unsigned long long*)(&Bs[cur][kk][tx * 4 + 66]);
#pragma unroll
            for (int i = 0; i < MI; i++)
#pragma unroll
                for (int jp = 0; jp < 4; jp++)
                    fma_f32x2(acc2[i][jp], ad[i], b2[jp]);
        }
        if (more) {
            int nxt = cur ^ 1;
            As[nxt][akc0 + 0][arow0] = pa0.x; As[nxt][akc0 + 1][arow0] = pa0.y;
            As[nxt][akc0 + 2][arow0] = pa0.z; As[nxt][akc0 + 3][arow0] = pa0.w;
            if constexpr (BM == 128) {
                As[nxt][akc0 + 0][arow1] = pa1.x; As[nxt][akc0 + 1][arow1] = pa1.y;
                As[nxt][akc0 + 2][arow1] = pa1.z; As[nxt][akc0 + 3][arow1] = pa1.w;
            }
            *(float4*)(&Bs[nxt][bkr0][bnc0]) = pb0;
            *(float4*)(&Bs[nxt][bkr1][bnc0]) = pb1;
            __syncthreads();
            cur = nxt;
        }
    }

    if constexpr (EPI == 0) {
        // vectorized epilogue: jp pairs (0,1) and (2,3) are contiguous quads in n
        float4 bq[2];
        if (bias) {
            bq[0] = *(const float4*)(bias + n0 + tx * 4);
            bq[1] = *(const float4*)(bias + n0 + tx * 4 + 64);
        }
#pragma unroll
        for (int i = 0; i < MI; i++) {
            int m = m0 + ((BM == 128) ? (ty * 4 + (i & 3) + (i >> 2) * 64) : (ty * 4 + i));
            if (m >= M) continue;
#pragma unroll
            for (int half = 0; half < 2; half++) {
                float4 v;
                unpack2(acc2[i][half * 2 + 0], v.x, v.y);
                unpack2(acc2[i][half * 2 + 1], v.z, v.w);
                if (bias) {
                    v.x += bq[half].x; v.y += bq[half].y;
                    v.z += bq[half].z; v.w += bq[half].w;
                }
                *(float4*)(C + (long)m * ldc + n0 + tx * 4 + half * 64) = v;
            }
        }
    } else {
        // EPI == 3: transposed store staged through smem, 8 chunks of 16 n-rows.
        // buf[nl][m] with row stride 130 (conflict-free scatter phase, stride-1 copy).
        float* buf = &As[0][0][0];   // 4096 floats available; uses 16*130 = 2080
        __syncthreads();             // main loop's last As/Bs reads must complete
#pragma unroll
        for (int c = 0; c < 8; c++) {
            int g = c >> 2;                       // which 64-half of n
            if ((tx >> 2) == (c & 3)) {           // 4 of 16 tx participate
#pragma unroll
                for (int i = 0; i < MI; i++) {
                    int mL = ty * 4 + (i & 3) + (i >> 2) * 64;
#pragma unroll
                    for (int jh = 0; jh < 2; jh++) {
                        int jp = g * 2 + jh;
                        float lo, hi;
                        unpack2(acc2[i][jp], lo, hi);
                        int nl0 = (tx & 3) * 4 + jh * 2;   // n within chunk
                        buf[nl0 * 130 + mL] = lo;
                        buf[(nl0 + 1) * 130 + mL] = hi;
                    }
                }
            }
            __syncthreads();
            // coalesced copy: 16 rows x 128 floats
#pragma unroll
            for (int it = 0; it < 8; it++) {
                int t = tid + it * 256;
                int nr = t >> 7, m = t & 127;
                C[(long)(c * 16 + nr) * ldc + m0 + m] = buf[nr * 130 + m];
            }
            __syncthreads();
        }
    }
}

// ---------------- softmax over S per (b,c) row (float4 vectorized) ----------------
__global__ void __launch_bounds__(256) k_softmax() {
    int c = blockIdx.x, b = blockIdx.y;
    __shared__ float4 sv[Sn / 4];
    __shared__ float red[256];
    int tid = threadIdx.x;
    int len = g_len[b];
    const float4* src = (const float4*)(g_scores + (long)c * (Bn * Sn) + (long)b * Sn);
    float mx = -3.4e38f;
#pragma unroll
    for (int it = 0; it < 2; it++) {
        int s4 = tid + it * 256;
        float4 v = src[s4];
        int s = s4 * 4;
        v.x = (s + 0 < len) ? v.x : -3.4e38f;
        v.y = (s + 1 < len) ? v.y : -3.4e38f;
        v.z = (s + 2 < len) ? v.z : -3.4e38f;
        v.w = (s + 3 < len) ? v.w : -3.4e38f;
        sv[s4] = v;
        mx = fmaxf(mx, fmaxf(fmaxf(v.x, v.y), fmaxf(v.z, v.w)));
    }
    red[tid] = mx; __syncthreads();
    for (int o = 128; o > 0; o >>= 1) { if (tid < o) red[tid] = fmaxf(red[tid], red[tid + o]); __syncthreads(); }
    float M = red[0]; __syncthreads();
    float sum = 0.f;
#pragma unroll
    for (int it = 0; it < 2; it++) {
        int s4 = tid + it * 256;
        float4 v = sv[s4];
        int s = s4 * 4;
        v.x = (s + 0 < len) ? __expf(v.x - M) : 0.f;
        v.y = (s + 1 < len) ? __expf(v.y - M) : 0.f;
        v.z = (s + 2 < len) ? __expf(v.z - M) : 0.f;
        v.w = (s + 3 < len) ? __expf(v.w - M) : 0.f;
        sv[s4] = v;
        sum += v.x + v.y + v.z + v.w;
    }
    red[tid] = sum; __syncthreads();
    for (int o = 128; o > 0; o >>= 1) { if (tid < o) red[tid] += red[tid + o]; __syncthreads(); }
    float inv = 1.f / red[0];
    float4* dst = (float4*)(g_attn + ((long)b * Cn + c) * Sn);
#pragma unroll
    for (int it = 0; it < 2; it++) {
        int s4 = tid + it * 256;
        float4 v = sv[s4];
        v.x *= inv; v.y *= inv; v.z *= inv; v.w *= inv;
        dst[s4] = v;
    }
}

// ---------------- ctx[b,p,h*64+dd] = Wv_head @ (ph0+ph1) + bv (float4 dots) ----------------
// also reduces the pooling split-K partials while staging into smem
__global__ void __launch_bounds__(256) k_ctx(const float* __restrict__ ipw,
                                             const float* __restrict__ ipb) {
    int b = blockIdx.x, h = blockIdx.y;
    __shared__ float sph[Pn * Dn];
    int tid = threadIdx.x;
    const float4* ph0 = (const float4*)(g_ph + ((long)b * Cn + h * Pn) * Dn);
    const float4* ph1 = (const float4*)(g_ph + ((long)(Bn + b) * Cn + h * Pn) * Dn);
    for (int i = tid; i < Pn * Dn / 4; i += 256) {
        float4 a = ph0[i], c = ph1[i];
        a.x += c.x; a.y += c.y; a.z += c.z; a.w += c.w;
        ((float4*)sph)[i] = a;
    }
    __syncthreads();
    const float* Wv = ipw + (long)2 * Dn * Dn;
    const float* bv = ipb + 2 * Dn;
    int warp = tid >> 5, lane = tid & 31;
    for (int o = warp; o < Pn * HDn; o += 8) {
        int p = o >> 6, dd = o & 63;
        const float4* wrow = (const float4*)(Wv + (long)(h * HDn + dd) * Dn);
        const float4* pr = (const float4*)(sph + p * Dn);
        float acc = 0.f;
#pragma unroll
        for (int d4 = lane; d4 < Dn / 4; d4 += 32) {
            float4 w4 = wrow[d4];
            float4 p4 = pr[d4];
            acc += w4.x * p4.x + w4.y * p4.y + w4.z * p4.z + w4.w * p4.w;
        }
        for (int off = 16; off > 0; off >>= 1) acc += __shfl_down_sync(0xffffffffu, acc, off);
        if (lane == 0)
            g_ctx[((long)b * Pn + p) * Dn + h * HDn + dd] = acc + bv[h * HDn + dd];
    }
}

// ---------------- build summary tokens + both layernorms -> xhat, maskf ----------------
// Register-resident: each thread owns 4 contiguous floats of the 1024-dim token.
// pma branch reduces the pooled split-K partials inline.
__global__ void __launch_bounds__(256)
k_summary(const float* __restrict__ hidden, const float* __restrict__ queries,
          const float* __restrict__ gpma, const float* __restrict__ bpma,
          const float* __restrict__ outb) {
    int l = blockIdx.x, b = blockIdx.y;
    __shared__ float red[256];
    int tid = threadIdx.x;
    float maskv = 1.f;
    float4 t = make_float4(0.f, 0.f, 0.f, 0.f);
    if (l == 0) {                       // cls token (len >= 1 always)
        t = ((const float4*)(hidden + (long)b * Sn * Dn))[tid];
    } else if (l <= Pn) {               // pma token: LN_pma(queries[p] + pooled[b,p])
        int p = l - 1;
        int row = b * Pn + p;           // pooled row in [0,128)
        float4 s = ((const float4*)outb)[tid];
#pragma unroll
        for (int z = 0; z < KSPLIT; z++) {
            float4 pp = ((const float4*)(g_part + ((long)z * Cn + row) * Dn))[tid];
            s.x += pp.x; s.y += pp.y; s.z += pp.z; s.w += pp.w;
        }
        float4 q4 = ((const float4*)(queries + (long)p * Dn))[tid];
        t.x = q4.x + s.x; t.y = q4.y + s.y; t.z = q4.z + s.z; t.w = q4.w + s.w;
        // LN_pma with affine
        float mu = blk_sum(t.x + t.y + t.z + t.w, red, tid) * (1.f / Dn);
        float dx = t.x - mu, dy = t.y - mu, dz = t.z - mu, dw = t.w - mu;
        float var = blk_sum(dx * dx + dy * dy + dz * dz + dw * dw, red, tid) * (1.f / Dn);
        float rs = rsqrtf(var + LNEPS);
        float4 g4 = ((const float4*)gpma)[tid];
        float4 b4 = ((const float4*)bpma)[tid];
        t.x = dx * rs * g4.x + b4.x; t.y = dy * rs * g4.y + b4.y;
        t.z = dz * rs * g4.z + b4.z; t.w = dw * rs * g4.w + b4.w;
    } else {                            // recent token j: hidden[b, len-64+j] if index >= 1
        int j = l - 1 - Pn;
        int idx = g_len[b] - Rn + j;
        if (idx >= 1) {
            t = ((const float4*)(hidden + ((long)b * Sn + idx) * Dn))[tid];
        } else {
            maskv = 0.f;
        }
    }
    // second LN (affines folded into WtVG/biasVG): xhat only
    float mu = blk_sum(t.x + t.y + t.z + t.w, red, tid) * (1.f / Dn);
    float dx = t.x - mu, dy = t.y - mu, dz = t.z - mu, dw = t.w - mu;
    float var = blk_sum(dx * dx + dy * dy + dz * dz + dw * dw, red, tid) * (1.f / Dn);
    float rs = rsqrtf(var + LNEPS);
    long row = (long)b * Ln + l;
    float4 xo;
    xo.x = dx * rs; xo.y = dy * rs; xo.z = dz * rs; xo.w = dw * rs;
    ((float4*)(g_xhat + row * Dn))[tid] = xo;
    if (tid == 0) g_maskf[row] = maskv;
}

// gated = sigmoid(gate) * silu(val) * mask (float4 vectorized); optionally writes
// the mask tail (fused k_maskout).
__global__ void k_gate(float* __restrict__ out, int writeMask) {
    int i = blockIdx.x * 256 + threadIdx.x;   // float4 index over Bn*Ln*Dn/4
    if (i >= Bn * Ln * Dn / 4) return;
    int m = i >> 8;                 // Dn/4 = 256 float4 per row
    int n4 = i & 255;
    const float4* vrow = (const float4*)(g_vg + (long)m * (2 * Dn));
    float4 v = vrow[n4];
    float4 g = vrow[Dn / 4 + n4];
    float mk = g_maskf[m];
    float4 r;
    r.x = (1.f / (1.f + __expf(-g.x))) * (v.x / (1.f + __expf(-v.x))) * mk;
    r.y = (1.f / (1.f + __expf(-g.y))) * (v.y / (1.f + __expf(-v.y))) * mk;
    r.z = (1.f / (1.f + __expf(-g.z))) * (v.z / (1.f + __expf(-v.z))) * mk;
    r.w = (1.f / (1.f + __expf(-g.w))) * (v.w / (1.f + __expf(-v.w))) * mk;
    ((float4*)out)[i] = r;
    if (writeMask && i < Bn * Ln)
        out[Bn * Ln * Dn + i] = g_maskf[i];
}

// ---------------- host ----------------
extern "C" void kernel_launch(void* const* d_in, const int* in_sizes, int n_in,
                              void* d_out, int out_size) {
    const float* hidden  = (const float*)d_in[0];
    const unsigned char* vmask = (const unsigned char*)d_in[1];
    const float* queries = (const float*)d_in[2];
    const float* ipw     = (const float*)d_in[3];
    const float* ipb     = (const float*)d_in[4];
    const float* outw    = (const float*)d_in[5];
    const float* outb    = (const float*)d_in[6];
    const float* gpma    = (const float*)d_in[7];
    const float* bpma    = (const float*)d_in[8];
    const float* lnvg    = (const float*)d_in[9];
    const float* lnvb    = (const float*)d_in[10];
    const float* Wv      = (const float*)d_in[11];
    const float* bv      = (const float*)d_in[12];
    const float* lngg    = (const float*)d_in[13];
    const float* lngb    = (const float*)d_in[14];
    const float* Wg      = (const float*)d_in[15];
    const float* bg      = (const float*)d_in[16];
    float* out = (float*)d_out;

    float *pWtO, *pWtVG, *pBVG, *pQT, *pSc, *pAt, *pPh, *pCtx, *pPart, *pXh, *pVG;
    cudaGetSymbolAddress((void**)&pWtO, g_WtO);
    cudaGetSymbolAddress((void**)&pWtVG, g_WtVG);
    cudaGetSymbolAddress((void**)&pBVG, g_biasVG);
    cudaGetSymbolAddress((void**)&pQT, g_qtilT);
    cudaGetSymbolAddress((void**)&pSc, g_scores);
    cudaGetSymbolAddress((void**)&pAt, g_attn);
    cudaGetSymbolAddress((void**)&pPh, g_ph);
    cudaGetSymbolAddress((void**)&pCtx, g_ctx);
    cudaGetSymbolAddress((void**)&pPart, g_part);
    cudaGetSymbolAddress((void**)&pXh, g_xhat);
    cudaGetSymbolAddress((void**)&pVG, g_vg);

    // zero only the tail beyond gated + mask regions (k_gate writes both)
    int gatedN = Bn * Ln * Dn;
    int maskN = Bn * Ln;
    int writeMask = (out_size >= gatedN + maskN) ? 1 : 0;
    int covered = gatedN + (writeMask ? maskN : 0);
    if (out_size > covered) {
        int tail = out_size - covered;
        k_zero<<<(tail + 255) / 256, 256>>>(out + covered, tail);
    }
    k_lengths<<<1, 256>>>(vmask);
    k_qproj<<<1024, 256>>>(queries, ipw, ipb);
    k_qtil<<<Cn, 256>>>(ipw + (long)Dn * Dn);
    k_transpose3<<<dim3(32, 32, 3), dim3(32, 8)>>>(Wv, lnvg, Wg, lngg, outw, pWtVG, pWtO);
    k_bias2<<<2048, 256>>>(pBVG, Wv, lnvb, bv, Wg, lngb, bg);

    // scores^T = (hidden @ qtilT)^T : stored [128 x 32768], staged transposed store
    // (k-proj bias dropped exactly: softmax is shift-invariant per (b,c) row)
    k_gemm<3, 128><<<dim3(1, 256, 1), 256>>>(hidden, pQT, pSc, Bn * Sn, Cn, Dn,
                                             Dn, Cn, Bn * Sn, 1,
                                             0, 0, 0, 0, 0, 0, nullptr);
    k_softmax<<<dim3(Cn, Bn), 256>>>();
    // pooling split-K x2: ph[z][b] = attn[b][:, z*1024:(z+1)*1024] @ hidden[b][z*1024:...]
    k_gemm<0, 128><<<dim3(8, 1, Bn * PSPLIT), 256>>>(
        pAt, hidden, pPh, Cn, Dn, Sn / PSPLIT,
        Sn, Dn, Dn, PSPLIT,
        (long)Cn * Sn, (long)(Sn / PSPLIT),                 // A: batch, k-split
        (long)Sn * Dn, (long)(Sn / PSPLIT) * Dn,            // B: batch, k-split
        (long)Cn * Dn, (long)Bn * Cn * Dn,                  // C: batch, k-split
        nullptr);
    k_ctx<<<dim3(Bn, Hn), 256>>>(ipw, ipb);
    // pooled (split-K x8): part[z] = ctx[:, z*128:(z+1)*128] @ WtO[z*128:(z+1)*128, :]
    k_gemm<0, 128><<<dim3(8, 1, KSPLIT), 256>>>(pCtx, pWtO, pPart, Cn, Dn, Dn / KSPLIT,
                                                Dn, Dn, Dn, 1,
                                                Dn / KSPLIT, 0,
                                                (long)(Dn / KSPLIT) * Dn, 0,
                                                (long)Cn * Dn, 0, nullptr);
    k_summary<<<dim3(Ln, Bn), 256>>>(hidden, queries, gpma, bpma, outb);
    // fused val|gate: vg = xhat @ [WtV|WtG] + biasVG : [1168 x 2048], BM=64 tiles
    k_gemm<0, 64><<<dim3(16, 19, 1), 256>>>(pXh, pWtVG, pVG, Bn * Ln, 2 * Dn, Dn,
                                            Dn, 2 * Dn, 2 * Dn, 1,
                                            0, 0, 0, 0, 0, 0, pBVG);
    k_gate<<<(Bn * Ln * Dn / 4 + 255) / 256, 256>>>(out, writeMask);
}